// round 4
// baseline (speedup 1.0000x reference)
#include <cuda_runtime.h>
#include <math.h>

#define MAXL 12288
#define SPLITS 32
#define ROWS_PER_SPLIT 384          // MAXL / SPLITS, divisible by 8
#define K1_THREADS 256
#define K2_THREADS 256
#define MAXBLK 256

// scratch: partial sums per row-split: [split][b(0..7)=acc, 8=count][column]
__device__ float g_part[SPLITS][9][MAXL];
// per-block partial squared-diff sums from k2
__device__ float g_bsum[MAXBLK][8];

__device__ __forceinline__ unsigned f2u(float x) { return __float_as_uint(x); }

// ---------------------------------------------------------------------------
// k1: masked column accumulation. One thread = 4 columns (float4).
// Semantics identical to the R2-passing scalar kernel, only load width changed:
//   per element: if (m != 0) { cnt += 1; acc[b] += p[b][i] * a; }
// ---------------------------------------------------------------------------
__global__ void k1_masked_gemv(const float*  __restrict__ predicts,
                               const float4* __restrict__ adj4,
                               const float4* __restrict__ mask4,
                               int L)
{
    const int L4 = L >> 2;
    const int j4 = blockIdx.x * K1_THREADS + threadIdx.x;   // float4 col index
    if (j4 >= L4) return;

    const int i0 = blockIdx.y * ROWS_PER_SPLIT;
    const int i1 = i0 + ROWS_PER_SPLIT;

    float4 acc[8];
    #pragma unroll
    for (int b = 0; b < 8; b++) acc[b] = make_float4(0.f, 0.f, 0.f, 0.f);
    float4 cnt = make_float4(0.f, 0.f, 0.f, 0.f);

    for (int i = i0; i < i1; i += 8) {
        // front-batch 8 independent float4 mask loads (8 x LDG.128 in flight)
        float4 m[8];
        #pragma unroll
        for (int u = 0; u < 8; u++)
            m[u] = __ldg(mask4 + (long long)(i + u) * L4 + j4);

        unsigned any = 0;
        #pragma unroll
        for (int u = 0; u < 8; u++)
            any |= f2u(m[u].x) | f2u(m[u].y) | f2u(m[u].z) | f2u(m[u].w);
        if (!any) continue;

        #pragma unroll
        for (int u = 0; u < 8; u++) {
            unsigned su = f2u(m[u].x) | f2u(m[u].y) | f2u(m[u].z) | f2u(m[u].w);
            if (su) {
                int ii = i + u;
                float4 a = __ldg(adj4 + (long long)ii * L4 + j4);
                float pb[8];
                #pragma unroll
                for (int b = 0; b < 8; b++)
                    pb[b] = __ldg(&predicts[b * L + ii]);

                if (f2u(m[u].x)) {
                    cnt.x += 1.f;
                    #pragma unroll
                    for (int b = 0; b < 8; b++) acc[b].x = fmaf(pb[b], a.x, acc[b].x);
                }
                if (f2u(m[u].y)) {
                    cnt.y += 1.f;
                    #pragma unroll
                    for (int b = 0; b < 8; b++) acc[b].y = fmaf(pb[b], a.y, acc[b].y);
                }
                if (f2u(m[u].z)) {
                    cnt.z += 1.f;
                    #pragma unroll
                    for (int b = 0; b < 8; b++) acc[b].z = fmaf(pb[b], a.z, acc[b].z);
                }
                if (f2u(m[u].w)) {
                    cnt.w += 1.f;
                    #pragma unroll
                    for (int b = 0; b < 8; b++) acc[b].w = fmaf(pb[b], a.w, acc[b].w);
                }
            }
        }
    }

    const int s = blockIdx.y;
    #pragma unroll
    for (int b = 0; b < 8; b++)
        reinterpret_cast<float4*>(&g_part[s][b][0])[j4] = acc[b];
    reinterpret_cast<float4*>(&g_part[s][8][0])[j4] = cnt;
}

// ---------------------------------------------------------------------------
// k2: per-column epilogue. Reduce splits, add identity term, divide by counts,
// diff = p - sim @ cand, block-reduce the 8 per-batch squared sums.
// ---------------------------------------------------------------------------
__global__ void __launch_bounds__(K2_THREADS)
k2_epilogue(const float* __restrict__ predicts,
            const float* __restrict__ sim,
            const float* __restrict__ mask,
            int L)
{
    __shared__ float s_sim[64];
    __shared__ float s_red[K2_THREADS / 32][8];

    int tid = threadIdx.x;
    if (tid < 64) s_sim[tid] = sim[tid];
    __syncthreads();

    int j = blockIdx.x * K2_THREADS + tid;
    float sq[8];
    #pragma unroll
    for (int b = 0; b < 8; b++) sq[b] = 0.f;

    if (j < L) {
        float acc[9];
        #pragma unroll
        for (int b = 0; b < 9; b++) acc[b] = 0.f;
        for (int s = 0; s < SPLITS; s++) {
            #pragma unroll
            for (int b = 0; b < 9; b++) acc[b] += g_part[s][b][j];
        }
        float mjj   = mask[(long long)j * L + j];
        float extra = 1.f - mjj;
        float inv_c = 1.f / (acc[8] + extra);   // counts[j] >= 1 always

        float p[8], cand[8];
        #pragma unroll
        for (int b = 0; b < 8; b++) {
            p[b]    = predicts[b * L + j];
            cand[b] = (acc[b] + p[b] * extra) * inv_c;
        }
        #pragma unroll
        for (int b = 0; b < 8; b++) {
            float d = p[b];
            #pragma unroll
            for (int bb = 0; bb < 8; bb++)
                d = fmaf(-s_sim[b * 8 + bb], cand[bb], d);
            sq[b] = d * d;
        }
    }

    int lane = tid & 31, warp = tid >> 5;
    #pragma unroll
    for (int b = 0; b < 8; b++) {
        float v = sq[b];
        #pragma unroll
        for (int off = 16; off > 0; off >>= 1)
            v += __shfl_xor_sync(0xFFFFFFFFu, v, off);
        if (lane == 0) s_red[warp][b] = v;
    }
    __syncthreads();
    if (warp == 0) {
        #pragma unroll
        for (int b = 0; b < 8; b++) {
            float v = (lane < K2_THREADS / 32) ? s_red[lane][b] : 0.f;
            #pragma unroll
            for (int off = 4; off > 0; off >>= 1)
                v += __shfl_xor_sync(0xFFFFFFFFu, v, off);
            if (lane == 0) g_bsum[blockIdx.x][b] = v;
        }
    }
}

// ---------------------------------------------------------------------------
// k3: final scalar. norms = sqrt(sumsq[b]); valid = rowsum(sim) != 0.
// ---------------------------------------------------------------------------
__global__ void k3_final(const float* __restrict__ sim,
                         float* __restrict__ out,
                         int nblocks)
{
    if (threadIdx.x != 0 || blockIdx.x != 0) return;
    float total = 0.f, cnt = 0.f;
    for (int b = 0; b < 8; b++) {
        float ss = 0.f;
        for (int k = 0; k < nblocks; k++) ss += g_bsum[k][b];
        float rs = 0.f;
        for (int bb = 0; bb < 8; bb++) rs += sim[b * 8 + bb];
        if (rs != 0.f) {
            total += sqrtf(ss);
            cnt   += 1.f;
        }
    }
    out[0] = (cnt == 0.f) ? 0.f : total / fmaxf(cnt, 1.f);
}

// ---------------------------------------------------------------------------
extern "C" void kernel_launch(void* const* d_in, const int* in_sizes, int n_in,
                              void* d_out, int out_size)
{
    const float* predicts = (const float*)d_in[0];
    const float* sim      = (const float*)d_in[1];
    const float* adj      = (const float*)d_in[2];
    const float* mask     = (const float*)d_in[3];
    float*       out      = (float*)d_out;

    const int B = 8;
    const int L = in_sizes[0] / B;        // 12288

    int colblocks = ((L / 4) + K1_THREADS - 1) / K1_THREADS;   // 12
    dim3 g1(colblocks, SPLITS);                                // 12 x 32 = 384
    k1_masked_gemv<<<g1, K1_THREADS>>>(predicts,
                                       (const float4*)adj,
                                       (const float4*)mask, L);

    int k2blocks = (L + K2_THREADS - 1) / K2_THREADS;          // 48
    k2_epilogue<<<k2blocks, K2_THREADS>>>(predicts, sim, mask, L);

    k3_final<<<1, 32>>>(sim, out, k2blocks);
}

// round 6
// speedup vs baseline: 1.1682x; 1.1682x over previous
#include <cuda_runtime.h>
#include <math.h>

#define MAXL 12288
#define SPLITS 32
#define ROWS_PER_SPLIT 384          // MAXL / SPLITS, divisible by 8
#define K1_THREADS 256
#define K2_THREADS 256
#define MAXBLK 256

// scratch: partial sums per row-split: [split][b(0..7)=acc, 8=count][column]
__device__ float g_part[SPLITS][9][MAXL];
// per-block partial squared-diff sums from k2
__device__ float g_bsum[MAXBLK][8];

__device__ __forceinline__ unsigned f2u(float x) { return __float_as_uint(x); }

// ---------------------------------------------------------------------------
// k1: masked column accumulation. One thread = 4 columns (float4).
// Identical semantics to the R4-passing kernel. Single change: the adj loads
// for the whole 8-row batch are issued as one predicated batch (8 independent
// LDG.128) instead of being serialized inside the processing branches.
// ---------------------------------------------------------------------------
__global__ void k1_masked_gemv(const float*  __restrict__ predicts,
                               const float4* __restrict__ adj4,
                               const float4* __restrict__ mask4,
                               int L)
{
    const int L4 = L >> 2;
    const int j4 = blockIdx.x * K1_THREADS + threadIdx.x;   // float4 col index
    if (j4 >= L4) return;

    const int i0 = blockIdx.y * ROWS_PER_SPLIT;
    const int i1 = i0 + ROWS_PER_SPLIT;

    float4 acc[8];
    #pragma unroll
    for (int b = 0; b < 8; b++) acc[b] = make_float4(0.f, 0.f, 0.f, 0.f);
    float4 cnt = make_float4(0.f, 0.f, 0.f, 0.f);

    for (int i = i0; i < i1; i += 8) {
        // ---- batch 1: 8 independent float4 mask loads ----
        float4 m[8];
        #pragma unroll
        for (int u = 0; u < 8; u++)
            m[u] = __ldg(mask4 + (long long)(i + u) * L4 + j4);

        unsigned su[8];
        #pragma unroll
        for (int u = 0; u < 8; u++)
            su[u] = f2u(m[u].x) | f2u(m[u].y) | f2u(m[u].z) | f2u(m[u].w);

        unsigned any = su[0] | su[1] | su[2] | su[3] |
                       su[4] | su[5] | su[6] | su[7];
        if (!any) continue;

        // ---- batch 2: 8 independent predicated adj loads ----
        float4 a[8];
        #pragma unroll
        for (int u = 0; u < 8; u++) {
            a[u] = make_float4(0.f, 0.f, 0.f, 0.f);
            if (su[u])
                a[u] = __ldg(adj4 + (long long)(i + u) * L4 + j4);
        }

        // ---- process: exactly the R4 bodies ----
        #pragma unroll
        for (int u = 0; u < 8; u++) {
            if (su[u]) {
                int ii = i + u;
                float pb[8];
                #pragma unroll
                for (int b = 0; b < 8; b++)
                    pb[b] = __ldg(&predicts[b * L + ii]);

                if (f2u(m[u].x)) {
                    cnt.x += 1.f;
                    #pragma unroll
                    for (int b = 0; b < 8; b++) acc[b].x = fmaf(pb[b], a[u].x, acc[b].x);
                }
                if (f2u(m[u].y)) {
                    cnt.y += 1.f;
                    #pragma unroll
                    for (int b = 0; b < 8; b++) acc[b].y = fmaf(pb[b], a[u].y, acc[b].y);
                }
                if (f2u(m[u].z)) {
                    cnt.z += 1.f;
                    #pragma unroll
                    for (int b = 0; b < 8; b++) acc[b].z = fmaf(pb[b], a[u].z, acc[b].z);
                }
                if (f2u(m[u].w)) {
                    cnt.w += 1.f;
                    #pragma unroll
                    for (int b = 0; b < 8; b++) acc[b].w = fmaf(pb[b], a[u].w, acc[b].w);
                }
            }
        }
    }

    const int s = blockIdx.y;
    #pragma unroll
    for (int b = 0; b < 8; b++)
        reinterpret_cast<float4*>(&g_part[s][b][0])[j4] = acc[b];
    reinterpret_cast<float4*>(&g_part[s][8][0])[j4] = cnt;
}

// ---------------------------------------------------------------------------
// k2: per-column epilogue. Reduce splits, add identity term, divide by counts,
// diff = p - sim @ cand, block-reduce the 8 per-batch squared sums.
// ---------------------------------------------------------------------------
__global__ void __launch_bounds__(K2_THREADS)
k2_epilogue(const float* __restrict__ predicts,
            const float* __restrict__ sim,
            const float* __restrict__ mask,
            int L)
{
    __shared__ float s_sim[64];
    __shared__ float s_red[K2_THREADS / 32][8];

    int tid = threadIdx.x;
    if (tid < 64) s_sim[tid] = sim[tid];
    __syncthreads();

    int j = blockIdx.x * K2_THREADS + tid;
    float sq[8];
    #pragma unroll
    for (int b = 0; b < 8; b++) sq[b] = 0.f;

    if (j < L) {
        float acc[9];
        #pragma unroll
        for (int b = 0; b < 9; b++) acc[b] = 0.f;
        for (int s = 0; s < SPLITS; s++) {
            #pragma unroll
            for (int b = 0; b < 9; b++) acc[b] += g_part[s][b][j];
        }
        float mjj   = mask[(long long)j * L + j];
        float extra = 1.f - mjj;
        float inv_c = 1.f / (acc[8] + extra);   // counts[j] >= 1 always

        float p[8], cand[8];
        #pragma unroll
        for (int b = 0; b < 8; b++) {
            p[b]    = predicts[b * L + j];
            cand[b] = (acc[b] + p[b] * extra) * inv_c;
        }
        #pragma unroll
        for (int b = 0; b < 8; b++) {
            float d = p[b];
            #pragma unroll
            for (int bb = 0; bb < 8; bb++)
                d = fmaf(-s_sim[b * 8 + bb], cand[bb], d);
            sq[b] = d * d;
        }
    }

    int lane = tid & 31, warp = tid >> 5;
    #pragma unroll
    for (int b = 0; b < 8; b++) {
        float v = sq[b];
        #pragma unroll
        for (int off = 16; off > 0; off >>= 1)
            v += __shfl_xor_sync(0xFFFFFFFFu, v, off);
        if (lane == 0) s_red[warp][b] = v;
    }
    __syncthreads();
    if (warp == 0) {
        #pragma unroll
        for (int b = 0; b < 8; b++) {
            float v = (lane < K2_THREADS / 32) ? s_red[lane][b] : 0.f;
            #pragma unroll
            for (int off = 4; off > 0; off >>= 1)
                v += __shfl_xor_sync(0xFFFFFFFFu, v, off);
            if (lane == 0) g_bsum[blockIdx.x][b] = v;
        }
    }
}

// ---------------------------------------------------------------------------
// k3: final scalar. norms = sqrt(sumsq[b]); valid = rowsum(sim) != 0.
// ---------------------------------------------------------------------------
__global__ void k3_final(const float* __restrict__ sim,
                         float* __restrict__ out,
                         int nblocks)
{
    if (threadIdx.x != 0 || blockIdx.x != 0) return;
    float total = 0.f, cnt = 0.f;
    for (int b = 0; b < 8; b++) {
        float ss = 0.f;
        for (int k = 0; k < nblocks; k++) ss += g_bsum[k][b];
        float rs = 0.f;
        for (int bb = 0; bb < 8; bb++) rs += sim[b * 8 + bb];
        if (rs != 0.f) {
            total += sqrtf(ss);
            cnt   += 1.f;
        }
    }
    out[0] = (cnt == 0.f) ? 0.f : total / fmaxf(cnt, 1.f);
}

// ---------------------------------------------------------------------------
extern "C" void kernel_launch(void* const* d_in, const int* in_sizes, int n_in,
                              void* d_out, int out_size)
{
    const float* predicts = (const float*)d_in[0];
    const float* sim      = (const float*)d_in[1];
    const float* adj      = (const float*)d_in[2];
    const float* mask     = (const float*)d_in[3];
    float*       out      = (float*)d_out;

    const int B = 8;
    const int L = in_sizes[0] / B;        // 12288

    int colblocks = ((L / 4) + K1_THREADS - 1) / K1_THREADS;   // 12
    dim3 g1(colblocks, SPLITS);                                // 12 x 32 = 384
    k1_masked_gemv<<<g1, K1_THREADS>>>(predicts,
                                       (const float4*)adj,
                                       (const float4*)mask, L);

    int k2blocks = (L + K2_THREADS - 1) / K2_THREADS;          // 48
    k2_epilogue<<<k2blocks, K2_THREADS>>>(predicts, sim, mask, L);

    k3_final<<<1, 32>>>(sim, out, k2blocks);
}

// round 7
// speedup vs baseline: 1.5089x; 1.2917x over previous
#include <cuda_runtime.h>
#include <math.h>

#define MAXL 12288
#define SPLITS 32
#define ROWS_PER_SPLIT 384          // MAXL / SPLITS, divisible by 4
#define K1_THREADS 128
#define K2_THREADS 256
#define MAXBLK 256

// scratch: partial sums per row-split: [split][b(0..7)=acc, 8=count][column]
__device__ float g_part[SPLITS][9][MAXL];
// per-block partial squared-diff sums from k2
__device__ float g_bsum[MAXBLK][8];
// transposed predicts: [L][8] (row-major, so one row = 2 float4 loads)
__device__ float g_pt[MAXL * 8];

__device__ __forceinline__ unsigned f2u(float x) { return __float_as_uint(x); }

// ---------------------------------------------------------------------------
// k0: transpose predicts [8][L] -> [L][8] so k1 fetches all 8 batch values
// for a row with two LDG.128 instead of eight scalar LDGs.
// ---------------------------------------------------------------------------
__global__ void k0_transpose(const float* __restrict__ predicts, int L)
{
    int i = blockIdx.x * 256 + threadIdx.x;
    if (i < L) {
        #pragma unroll
        for (int b = 0; b < 8; b++)
            g_pt[i * 8 + b] = predicts[b * L + i];
    }
}

// ---------------------------------------------------------------------------
// k1: masked column accumulation. One thread = 4 columns (float4).
// R6 semantics preserved exactly (thresholded branches, cnt += 1.f).
// New: software-pipelined mask batches (double buffer, batch=4) and
// transposed predicts. 128-thread blocks for higher occupancy.
// ---------------------------------------------------------------------------
__global__ void k1_masked_gemv(const float4* __restrict__ adj4,
                               const float4* __restrict__ mask4,
                               int L)
{
    const int L4 = L >> 2;
    const int j4 = blockIdx.x * K1_THREADS + threadIdx.x;   // float4 col index
    if (j4 >= L4) return;

    const int i0 = blockIdx.y * ROWS_PER_SPLIT;
    const float4* mcol = mask4 + j4;
    const float4* acol = adj4  + j4;
    const float4* pt4  = reinterpret_cast<const float4*>(g_pt);

    float4 acc[8];
    #pragma unroll
    for (int b = 0; b < 8; b++) acc[b] = make_float4(0.f, 0.f, 0.f, 0.f);
    float4 cnt = make_float4(0.f, 0.f, 0.f, 0.f);

    // pipeline prologue: first mask batch
    float4 mn[4];
    #pragma unroll
    for (int u = 0; u < 4; u++)
        mn[u] = __ldg(mcol + (long long)(i0 + u) * L4);

    for (int r0 = 0; r0 < ROWS_PER_SPLIT; r0 += 4) {
        const int i = i0 + r0;

        float4 m[4];
        #pragma unroll
        for (int u = 0; u < 4; u++) m[u] = mn[u];

        // prefetch next mask batch BEFORE processing current
        if (r0 + 4 < ROWS_PER_SPLIT) {
            #pragma unroll
            for (int u = 0; u < 4; u++)
                mn[u] = __ldg(mcol + (long long)(i + 4 + u) * L4);
        }

        unsigned su[4];
        #pragma unroll
        for (int u = 0; u < 4; u++)
            su[u] = f2u(m[u].x) | f2u(m[u].y) | f2u(m[u].z) | f2u(m[u].w);

        unsigned any = su[0] | su[1] | su[2] | su[3];
        if (!any) continue;

        // predicated adj batch (4 independent LDG.128)
        float4 a[4];
        #pragma unroll
        for (int u = 0; u < 4; u++) {
            a[u] = make_float4(0.f, 0.f, 0.f, 0.f);
            if (su[u])
                a[u] = __ldg(acol + (long long)(i + u) * L4);
        }

        // process: R6 bodies, predicts via 2 x LDG.128 from transposed layout
        #pragma unroll
        for (int u = 0; u < 4; u++) {
            if (su[u]) {
                int ii = i + u;
                float4 pA = __ldg(pt4 + ii * 2);
                float4 pB = __ldg(pt4 + ii * 2 + 1);
                float pb[8] = {pA.x, pA.y, pA.z, pA.w,
                               pB.x, pB.y, pB.z, pB.w};

                if (f2u(m[u].x)) {
                    cnt.x += 1.f;
                    #pragma unroll
                    for (int b = 0; b < 8; b++) acc[b].x = fmaf(pb[b], a[u].x, acc[b].x);
                }
                if (f2u(m[u].y)) {
                    cnt.y += 1.f;
                    #pragma unroll
                    for (int b = 0; b < 8; b++) acc[b].y = fmaf(pb[b], a[u].y, acc[b].y);
                }
                if (f2u(m[u].z)) {
                    cnt.z += 1.f;
                    #pragma unroll
                    for (int b = 0; b < 8; b++) acc[b].z = fmaf(pb[b], a[u].z, acc[b].z);
                }
                if (f2u(m[u].w)) {
                    cnt.w += 1.f;
                    #pragma unroll
                    for (int b = 0; b < 8; b++) acc[b].w = fmaf(pb[b], a[u].w, acc[b].w);
                }
            }
        }
    }

    const int s = blockIdx.y;
    #pragma unroll
    for (int b = 0; b < 8; b++)
        reinterpret_cast<float4*>(&g_part[s][b][0])[j4] = acc[b];
    reinterpret_cast<float4*>(&g_part[s][8][0])[j4] = cnt;
}

// ---------------------------------------------------------------------------
// k2: per-column epilogue. Reduce splits, add identity term, divide by counts,
// diff = p - sim @ cand, block-reduce the 8 per-batch squared sums.
// ---------------------------------------------------------------------------
__global__ void __launch_bounds__(K2_THREADS)
k2_epilogue(const float* __restrict__ predicts,
            const float* __restrict__ sim,
            const float* __restrict__ mask,
            int L)
{
    __shared__ float s_sim[64];
    __shared__ float s_red[K2_THREADS / 32][8];

    int tid = threadIdx.x;
    if (tid < 64) s_sim[tid] = sim[tid];
    __syncthreads();

    int j = blockIdx.x * K2_THREADS + tid;
    float sq[8];
    #pragma unroll
    for (int b = 0; b < 8; b++) sq[b] = 0.f;

    if (j < L) {
        float acc[9];
        #pragma unroll
        for (int b = 0; b < 9; b++) acc[b] = 0.f;
        for (int s = 0; s < SPLITS; s++) {
            #pragma unroll
            for (int b = 0; b < 9; b++) acc[b] += g_part[s][b][j];
        }
        float mjj   = mask[(long long)j * L + j];
        float extra = 1.f - mjj;
        float inv_c = 1.f / (acc[8] + extra);   // counts[j] >= 1 always

        float p[8], cand[8];
        #pragma unroll
        for (int b = 0; b < 8; b++) {
            p[b]    = predicts[b * L + j];
            cand[b] = (acc[b] + p[b] * extra) * inv_c;
        }
        #pragma unroll
        for (int b = 0; b < 8; b++) {
            float d = p[b];
            #pragma unroll
            for (int bb = 0; bb < 8; bb++)
                d = fmaf(-s_sim[b * 8 + bb], cand[bb], d);
            sq[b] = d * d;
        }
    }

    int lane = tid & 31, warp = tid >> 5;
    #pragma unroll
    for (int b = 0; b < 8; b++) {
        float v = sq[b];
        #pragma unroll
        for (int off = 16; off > 0; off >>= 1)
            v += __shfl_xor_sync(0xFFFFFFFFu, v, off);
        if (lane == 0) s_red[warp][b] = v;
    }
    __syncthreads();
    if (warp == 0) {
        #pragma unroll
        for (int b = 0; b < 8; b++) {
            float v = (lane < K2_THREADS / 32) ? s_red[lane][b] : 0.f;
            #pragma unroll
            for (int off = 4; off > 0; off >>= 1)
                v += __shfl_xor_sync(0xFFFFFFFFu, v, off);
            if (lane == 0) g_bsum[blockIdx.x][b] = v;
        }
    }
}

// ---------------------------------------------------------------------------
// k3: final scalar. norms = sqrt(sumsq[b]); valid = rowsum(sim) != 0.
// ---------------------------------------------------------------------------
__global__ void k3_final(const float* __restrict__ sim,
                         float* __restrict__ out,
                         int nblocks)
{
    if (threadIdx.x != 0 || blockIdx.x != 0) return;
    float total = 0.f, cnt = 0.f;
    for (int b = 0; b < 8; b++) {
        float ss = 0.f;
        for (int k = 0; k < nblocks; k++) ss += g_bsum[k][b];
        float rs = 0.f;
        for (int bb = 0; bb < 8; bb++) rs += sim[b * 8 + bb];
        if (rs != 0.f) {
            total += sqrtf(ss);
            cnt   += 1.f;
        }
    }
    out[0] = (cnt == 0.f) ? 0.f : total / fmaxf(cnt, 1.f);
}

// ---------------------------------------------------------------------------
extern "C" void kernel_launch(void* const* d_in, const int* in_sizes, int n_in,
                              void* d_out, int out_size)
{
    const float* predicts = (const float*)d_in[0];
    const float* sim      = (const float*)d_in[1];
    const float* adj      = (const float*)d_in[2];
    const float* mask     = (const float*)d_in[3];
    float*       out      = (float*)d_out;

    const int B = 8;
    const int L = in_sizes[0] / B;        // 12288

    k0_transpose<<<(L + 255) / 256, 256>>>(predicts, L);

    int colblocks = ((L / 4) + K1_THREADS - 1) / K1_THREADS;   // 24
    dim3 g1(colblocks, SPLITS);                                // 24 x 32 = 768
    k1_masked_gemv<<<g1, K1_THREADS>>>((const float4*)adj,
                                       (const float4*)mask, L);

    int k2blocks = (L + K2_THREADS - 1) / K2_THREADS;          // 48
    k2_epilogue<<<k2blocks, K2_THREADS>>>(predicts, sim, mask, L);

    k3_final<<<1, 32>>>(sim, out, k2blocks);
}

// round 8
// speedup vs baseline: 1.5408x; 1.0212x over previous
#include <cuda_runtime.h>
#include <math.h>

#define MAXL 12288
#define SPLITS 32
#define ROWS_PER_SPLIT 384          // MAXL / SPLITS, divisible by 4
#define K1_THREADS 128
#define STAGES 4                    // cp.async ring depth (3 in flight)
#define K2_THREADS 256
#define MAXBLK 256

// scratch: partial sums per row-split: [split][b(0..7)=acc, 8=count][column]
__device__ float g_part[SPLITS][9][MAXL];
// per-block partial squared-diff sums from k2
__device__ float g_bsum[MAXBLK][8];
// transposed predicts: [L][8] (row-major, so one row = 2 float4 loads)
__device__ float g_pt[MAXL * 8];

__device__ __forceinline__ unsigned f2u(float x) { return __float_as_uint(x); }

__device__ __forceinline__ void cp_async16(unsigned saddr, const void* gaddr) {
    asm volatile("cp.async.cg.shared.global [%0], [%1], 16;"
                 :: "r"(saddr), "l"(gaddr));
}
#define CP_COMMIT() asm volatile("cp.async.commit_group;" ::: "memory")
#define CP_WAIT2()  asm volatile("cp.async.wait_group 2;" ::: "memory")

// ---------------------------------------------------------------------------
// k0: transpose predicts [8][L] -> [L][8] so k1 fetches all 8 batch values
// for a row with two LDG.128 instead of eight scalar LDGs.
// ---------------------------------------------------------------------------
__global__ void k0_transpose(const float* __restrict__ predicts, int L)
{
    int i = blockIdx.x * 256 + threadIdx.x;
    if (i < L) {
        #pragma unroll
        for (int b = 0; b < 8; b++)
            g_pt[i * 8 + b] = predicts[b * L + i];
    }
}

// ---------------------------------------------------------------------------
// k1: masked column accumulation. One thread = 4 columns (float4).
// Mask streamed via a 4-stage cp.async ring into THREAD-PRIVATE smem
// (each thread reads back exactly the 16B chunks it copied -> no syncthreads).
// Stage issue + commit are unconditional so wait_group<2> semantics hold.
// Processing bodies identical to the R6/R7-passing kernels.
// ---------------------------------------------------------------------------
__global__ void k1_masked_gemv(const float4* __restrict__ adj4,
                               const float4* __restrict__ mask4,
                               int L)
{
    __shared__ float4 sm[STAGES][4][K1_THREADS];   // 32 KB

    const int L4 = L >> 2;
    const int j4 = blockIdx.x * K1_THREADS + threadIdx.x;  // grid is exact
    const int t  = threadIdx.x;
    const int i0 = blockIdx.y * ROWS_PER_SPLIT;

    const float4* mcol = mask4 + j4;
    const float4* acol = adj4  + j4;
    const float4* pt4  = reinterpret_cast<const float4*>(g_pt);

    float4 acc[8];
    #pragma unroll
    for (int b = 0; b < 8; b++) acc[b] = make_float4(0.f, 0.f, 0.f, 0.f);
    float4 cnt = make_float4(0.f, 0.f, 0.f, 0.f);

    // prologue: issue stages 0..STAGES-2
    #pragma unroll
    for (int s = 0; s < STAGES - 1; s++) {
        #pragma unroll
        for (int u = 0; u < 4; u++) {
            unsigned sa = (unsigned)__cvta_generic_to_shared(&sm[s][u][t]);
            cp_async16(sa, mcol + (long long)(i0 + s * 4 + u) * L4);
        }
        CP_COMMIT();
    }

    const int NIT = ROWS_PER_SPLIT / 4;    // 96
    for (int it = 0; it < NIT; it++) {
        const int stg = it & (STAGES - 1);
        CP_WAIT2();                         // oldest of 3 pending groups done

        float4 m[4];
        #pragma unroll
        for (int u = 0; u < 4; u++) m[u] = sm[stg][u][t];

        // issue next stage (or an empty group at the tail)
        const int nit = it + STAGES - 1;
        if (nit < NIT) {
            const int ns = nit & (STAGES - 1);
            #pragma unroll
            for (int u = 0; u < 4; u++) {
                unsigned sa = (unsigned)__cvta_generic_to_shared(&sm[ns][u][t]);
                cp_async16(sa, mcol + (long long)(i0 + nit * 4 + u) * L4);
            }
        }
        CP_COMMIT();

        unsigned su[4];
        #pragma unroll
        for (int u = 0; u < 4; u++)
            su[u] = f2u(m[u].x) | f2u(m[u].y) | f2u(m[u].z) | f2u(m[u].w);

        if (!(su[0] | su[1] | su[2] | su[3])) continue;

        const int i = i0 + it * 4;

        // predicated adj batch (4 independent LDG.128)
        float4 a[4];
        #pragma unroll
        for (int u = 0; u < 4; u++) {
            a[u] = make_float4(0.f, 0.f, 0.f, 0.f);
            if (su[u])
                a[u] = __ldg(acol + (long long)(i + u) * L4);
        }

        #pragma unroll
        for (int u = 0; u < 4; u++) {
            if (su[u]) {
                int ii = i + u;
                float4 pA = __ldg(pt4 + ii * 2);
                float4 pB = __ldg(pt4 + ii * 2 + 1);
                float pb[8] = {pA.x, pA.y, pA.z, pA.w,
                               pB.x, pB.y, pB.z, pB.w};

                if (f2u(m[u].x)) {
                    cnt.x += 1.f;
                    #pragma unroll
                    for (int b = 0; b < 8; b++) acc[b].x = fmaf(pb[b], a[u].x, acc[b].x);
                }
                if (f2u(m[u].y)) {
                    cnt.y += 1.f;
                    #pragma unroll
                    for (int b = 0; b < 8; b++) acc[b].y = fmaf(pb[b], a[u].y, acc[b].y);
                }
                if (f2u(m[u].z)) {
                    cnt.z += 1.f;
                    #pragma unroll
                    for (int b = 0; b < 8; b++) acc[b].z = fmaf(pb[b], a[u].z, acc[b].z);
                }
                if (f2u(m[u].w)) {
                    cnt.w += 1.f;
                    #pragma unroll
                    for (int b = 0; b < 8; b++) acc[b].w = fmaf(pb[b], a[u].w, acc[b].w);
                }
            }
        }
    }

    const int s = blockIdx.y;
    #pragma unroll
    for (int b = 0; b < 8; b++)
        reinterpret_cast<float4*>(&g_part[s][b][0])[j4] = acc[b];
    reinterpret_cast<float4*>(&g_part[s][8][0])[j4] = cnt;
}

// ---------------------------------------------------------------------------
// k2: per-column epilogue. Reduce splits, add identity term, divide by counts,
// diff = p - sim @ cand, block-reduce the 8 per-batch squared sums.
// ---------------------------------------------------------------------------
__global__ void __launch_bounds__(K2_THREADS)
k2_epilogue(const float* __restrict__ predicts,
            const float* __restrict__ sim,
            const float* __restrict__ mask,
            int L)
{
    __shared__ float s_sim[64];
    __shared__ float s_red[K2_THREADS / 32][8];

    int tid = threadIdx.x;
    if (tid < 64) s_sim[tid] = sim[tid];
    __syncthreads();

    int j = blockIdx.x * K2_THREADS + tid;
    float sq[8];
    #pragma unroll
    for (int b = 0; b < 8; b++) sq[b] = 0.f;

    if (j < L) {
        float acc[9];
        #pragma unroll
        for (int b = 0; b < 9; b++) acc[b] = 0.f;
        for (int s = 0; s < SPLITS; s++) {
            #pragma unroll
            for (int b = 0; b < 9; b++) acc[b] += g_part[s][b][j];
        }
        float mjj   = mask[(long long)j * L + j];
        float extra = 1.f - mjj;
        float inv_c = 1.f / (acc[8] + extra);   // counts[j] >= 1 always

        float p[8], cand[8];
        #pragma unroll
        for (int b = 0; b < 8; b++) {
            p[b]    = predicts[b * L + j];
            cand[b] = (acc[b] + p[b] * extra) * inv_c;
        }
        #pragma unroll
        for (int b = 0; b < 8; b++) {
            float d = p[b];
            #pragma unroll
            for (int bb = 0; bb < 8; bb++)
                d = fmaf(-s_sim[b * 8 + bb], cand[bb], d);
            sq[b] = d * d;
        }
    }

    int lane = tid & 31, warp = tid >> 5;
    #pragma unroll
    for (int b = 0; b < 8; b++) {
        float v = sq[b];
        #pragma unroll
        for (int off = 16; off > 0; off >>= 1)
            v += __shfl_xor_sync(0xFFFFFFFFu, v, off);
        if (lane == 0) s_red[warp][b] = v;
    }
    __syncthreads();
    if (warp == 0) {
        #pragma unroll
        for (int b = 0; b < 8; b++) {
            float v = (lane < K2_THREADS / 32) ? s_red[lane][b] : 0.f;
            #pragma unroll
            for (int off = 4; off > 0; off >>= 1)
                v += __shfl_xor_sync(0xFFFFFFFFu, v, off);
            if (lane == 0) g_bsum[blockIdx.x][b] = v;
        }
    }
}

// ---------------------------------------------------------------------------
// k3: final scalar. norms = sqrt(sumsq[b]); valid = rowsum(sim) != 0.
// ---------------------------------------------------------------------------
__global__ void k3_final(const float* __restrict__ sim,
                         float* __restrict__ out,
                         int nblocks)
{
    if (threadIdx.x != 0 || blockIdx.x != 0) return;
    float total = 0.f, cnt = 0.f;
    for (int b = 0; b < 8; b++) {
        float ss = 0.f;
        for (int k = 0; k < nblocks; k++) ss += g_bsum[k][b];
        float rs = 0.f;
        for (int bb = 0; bb < 8; bb++) rs += sim[b * 8 + bb];
        if (rs != 0.f) {
            total += sqrtf(ss);
            cnt   += 1.f;
        }
    }
    out[0] = (cnt == 0.f) ? 0.f : total / fmaxf(cnt, 1.f);
}

// ---------------------------------------------------------------------------
extern "C" void kernel_launch(void* const* d_in, const int* in_sizes, int n_in,
                              void* d_out, int out_size)
{
    const float* predicts = (const float*)d_in[0];
    const float* sim      = (const float*)d_in[1];
    const float* adj      = (const float*)d_in[2];
    const float* mask     = (const float*)d_in[3];
    float*       out      = (float*)d_out;

    const int B = 8;
    const int L = in_sizes[0] / B;        // 12288

    k0_transpose<<<(L + 255) / 256, 256>>>(predicts, L);

    int colblocks = (L / 4) / K1_THREADS;                      // 24, exact
    dim3 g1(colblocks, SPLITS);                                // 24 x 32 = 768
    k1_masked_gemv<<<g1, K1_THREADS>>>((const float4*)adj,
                                       (const float4*)mask, L);

    int k2blocks = (L + K2_THREADS - 1) / K2_THREADS;          // 48
    k2_epilogue<<<k2blocks, K2_THREADS>>>(predicts, sim, mask, L);

    k3_final<<<1, 32>>>(sim, out, k2blocks);
}

// round 10
// speedup vs baseline: 1.6136x; 1.0472x over previous
#include <cuda_runtime.h>
#include <math.h>

#define MAXL 12288
#define SPLITS 64
#define ROWS_PER_SPLIT 192          // MAXL / SPLITS, divisible by 4
#define K1_THREADS 128
#define MSTAGES 3                   // mask cp.async ring depth
#define K2_THREADS 256
#define MAXBLK 256

// scratch: partial sums per row-split: [split][b(0..7)=acc, 8=count][column]
__device__ float g_part[SPLITS][9][MAXL];
// per-block partial squared-diff sums from k2
__device__ float g_bsum[MAXBLK][8];
// transposed predicts: [L][8] (row-major, so one row = 2 float4 loads)
__device__ float g_pt[MAXL * 8];

__device__ __forceinline__ unsigned f2u(float x) { return __float_as_uint(x); }

__device__ __forceinline__ void cp_async16(unsigned saddr, const void* gaddr) {
    asm volatile("cp.async.cg.shared.global [%0], [%1], 16;"
                 :: "r"(saddr), "l"(gaddr));
}
#define CP_COMMIT() asm volatile("cp.async.commit_group;" ::: "memory")
#define CP_WAIT1()  asm volatile("cp.async.wait_group 1;" ::: "memory")

// ---------------------------------------------------------------------------
// k0: transpose predicts [8][L] -> [L][8]
// ---------------------------------------------------------------------------
__global__ void k0_transpose(const float* __restrict__ predicts, int L)
{
    int i = blockIdx.x * 256 + threadIdx.x;
    if (i < L) {
        #pragma unroll
        for (int b = 0; b < 8; b++)
            g_pt[i * 8 + b] = predicts[b * L + i];
    }
}

// ---------------------------------------------------------------------------
// k1: masked column accumulation. One thread = 4 columns (float4).
// - mask: 3-stage cp.async ring, thread-private readback
// - adj:  predicated batch issued ONE ITERATION AHEAD (latency hidden)
// - predicts: CTA-local smem slice (LDS instead of L2 in the hot body)
// Gating semantics byte-for-byte R6/R7/R8 (thresholded, cnt += 1.f).
// ---------------------------------------------------------------------------
__global__ void k1_masked_gemv(const float4* __restrict__ adj4,
                               const float4* __restrict__ mask4,
                               int L)
{
    __shared__ float4 sm_mask[MSTAGES][4][K1_THREADS];      // 24 KB
    __shared__ float4 sm_pt[ROWS_PER_SPLIT][2];             // 6 KB

    const int L4 = L >> 2;
    const int j4 = blockIdx.x * K1_THREADS + threadIdx.x;   // grid exact
    const int t  = threadIdx.x;
    const int i0 = blockIdx.y * ROWS_PER_SPLIT;

    const float4* mcol = mask4 + j4;
    const float4* acol = adj4  + j4;
    const float4* ptg  = reinterpret_cast<const float4*>(g_pt) + i0 * 2;

    // ---- prologue ----
    // group P: predicts slice (384 x 16B chunks, 3 per thread)
    #pragma unroll
    for (int c = 0; c < 3; c++) {
        int idx = c * K1_THREADS + t;                       // 0..383
        unsigned sa = (unsigned)__cvta_generic_to_shared(&sm_pt[0][0] + idx);
        cp_async16(sa, ptg + idx);
    }
    CP_COMMIT();
    // groups 0,1: first two mask stages
    #pragma unroll
    for (int s = 0; s < 2; s++) {
        #pragma unroll
        for (int u = 0; u < 4; u++) {
            unsigned sa = (unsigned)__cvta_generic_to_shared(&sm_mask[s][u][t]);
            cp_async16(sa, mcol + (long long)(i0 + s * 4 + u) * L4);
        }
        CP_COMMIT();
    }
    CP_WAIT1();                 // P + stage0 done (stage1 pending)
    __syncthreads();            // sm_pt visible block-wide

    float4 acc[8];
    #pragma unroll
    for (int b = 0; b < 8; b++) acc[b] = make_float4(0.f, 0.f, 0.f, 0.f);
    float4 cnt = make_float4(0.f, 0.f, 0.f, 0.f);

    // iter 0 state: mask, su, adj-in-flight
    float4 m_cur[4];
    #pragma unroll
    for (int u = 0; u < 4; u++) m_cur[u] = sm_mask[0][u][t];
    unsigned su_cur[4];
    #pragma unroll
    for (int u = 0; u < 4; u++)
        su_cur[u] = f2u(m_cur[u].x) | f2u(m_cur[u].y) | f2u(m_cur[u].z) | f2u(m_cur[u].w);
    float4 a_cur[4];
    #pragma unroll
    for (int u = 0; u < 4; u++) {
        a_cur[u] = make_float4(0.f, 0.f, 0.f, 0.f);
        if (su_cur[u])
            a_cur[u] = __ldg(acol + (long long)(i0 + u) * L4);
    }

    const int NIT = ROWS_PER_SPLIT / 4;     // 48
    for (int it = 0; it < NIT; it++) {
        // issue mask stage it+2 (unconditional commit keeps group accounting)
        const int pst = it + 2;
        if (pst < NIT) {
            const int ps = pst % MSTAGES;
            #pragma unroll
            for (int u = 0; u < 4; u++) {
                unsigned sa = (unsigned)__cvta_generic_to_shared(&sm_mask[ps][u][t]);
                cp_async16(sa, mcol + (long long)(i0 + pst * 4 + u) * L4);
            }
        }
        CP_COMMIT();
        CP_WAIT1();                          // stage it+1 ready

        // read next mask, compute su, issue next adj batch (one iter ahead)
        float4 m_nxt[4];
        unsigned su_nxt[4];
        float4 a_nxt[4];
        if (it + 1 < NIT) {
            const int ns = (it + 1) % MSTAGES;
            #pragma unroll
            for (int u = 0; u < 4; u++) m_nxt[u] = sm_mask[ns][u][t];
            #pragma unroll
            for (int u = 0; u < 4; u++)
                su_nxt[u] = f2u(m_nxt[u].x) | f2u(m_nxt[u].y) |
                            f2u(m_nxt[u].z) | f2u(m_nxt[u].w);
            #pragma unroll
            for (int u = 0; u < 4; u++) {
                a_nxt[u] = make_float4(0.f, 0.f, 0.f, 0.f);
                if (su_nxt[u])
                    a_nxt[u] = __ldg(acol + (long long)(i0 + (it + 1) * 4 + u) * L4);
            }
        }

        // process current iteration (R6-proven bodies; predicts from smem)
        if (su_cur[0] | su_cur[1] | su_cur[2] | su_cur[3]) {
            const int r = it * 4;
            #pragma unroll
            for (int u = 0; u < 4; u++) {
                if (su_cur[u]) {
                    float4 pA = sm_pt[r + u][0];
                    float4 pB = sm_pt[r + u][1];
                    float pb[8] = {pA.x, pA.y, pA.z, pA.w,
                                   pB.x, pB.y, pB.z, pB.w};

                    if (f2u(m_cur[u].x)) {
                        cnt.x += 1.f;
                        #pragma unroll
                        for (int b = 0; b < 8; b++) acc[b].x = fmaf(pb[b], a_cur[u].x, acc[b].x);
                    }
                    if (f2u(m_cur[u].y)) {
                        cnt.y += 1.f;
                        #pragma unroll
                        for (int b = 0; b < 8; b++) acc[b].y = fmaf(pb[b], a_cur[u].y, acc[b].y);
                    }
                    if (f2u(m_cur[u].z)) {
                        cnt.z += 1.f;
                        #pragma unroll
                        for (int b = 0; b < 8; b++) acc[b].z = fmaf(pb[b], a_cur[u].z, acc[b].z);
                    }
                    if (f2u(m_cur[u].w)) {
                        cnt.w += 1.f;
                        #pragma unroll
                        for (int b = 0; b < 8; b++) acc[b].w = fmaf(pb[b], a_cur[u].w, acc[b].w);
                    }
                }
            }
        }

        // rotate pipeline state
        if (it + 1 < NIT) {
            #pragma unroll
            for (int u = 0; u < 4; u++) {
                m_cur[u]  = m_nxt[u];
                su_cur[u] = su_nxt[u];
                a_cur[u]  = a_nxt[u];
            }
        }
    }

    const int s = blockIdx.y;
    #pragma unroll
    for (int b = 0; b < 8; b++)
        reinterpret_cast<float4*>(&g_part[s][b][0])[j4] = acc[b];
    reinterpret_cast<float4*>(&g_part[s][8][0])[j4] = cnt;
}

// ---------------------------------------------------------------------------
// k2: per-column epilogue (unchanged, proven).
// ---------------------------------------------------------------------------
__global__ void __launch_bounds__(K2_THREADS)
k2_epilogue(const float* __restrict__ predicts,
            const float* __restrict__ sim,
            const float* __restrict__ mask,
            int L)
{
    __shared__ float s_sim[64];
    __shared__ float s_red[K2_THREADS / 32][8];

    int tid = threadIdx.x;
    if (tid < 64) s_sim[tid] = sim[tid];
    __syncthreads();

    int j = blockIdx.x * K2_THREADS + tid;
    float sq[8];
    #pragma unroll
    for (int b = 0; b < 8; b++) sq[b] = 0.f;

    if (j < L) {
        float acc[9];
        #pragma unroll
        for (int b = 0; b < 9; b++) acc[b] = 0.f;
        for (int s = 0; s < SPLITS; s++) {
            #pragma unroll
            for (int b = 0; b < 9; b++) acc[b] += g_part[s][b][j];
        }
        float mjj   = mask[(long long)j * L + j];
        float extra = 1.f - mjj;
        float inv_c = 1.f / (acc[8] + extra);

        float p[8], cand[8];
        #pragma unroll
        for (int b = 0; b < 8; b++) {
            p[b]    = predicts[b * L + j];
            cand[b] = (acc[b] + p[b] * extra) * inv_c;
        }
        #pragma unroll
        for (int b = 0; b < 8; b++) {
            float d = p[b];
            #pragma unroll
            for (int bb = 0; bb < 8; bb++)
                d = fmaf(-s_sim[b * 8 + bb], cand[bb], d);
            sq[b] = d * d;
        }
    }

    int lane = tid & 31, warp = tid >> 5;
    #pragma unroll
    for (int b = 0; b < 8; b++) {
        float v = sq[b];
        #pragma unroll
        for (int off = 16; off > 0; off >>= 1)
            v += __shfl_xor_sync(0xFFFFFFFFu, v, off);
        if (lane == 0) s_red[warp][b] = v;
    }
    __syncthreads();
    if (warp == 0) {
        #pragma unroll
        for (int b = 0; b < 8; b++) {
            float v = (lane < K2_THREADS / 32) ? s_red[lane][b] : 0.f;
            #pragma unroll
            for (int off = 4; off > 0; off >>= 1)
                v += __shfl_xor_sync(0xFFFFFFFFu, v, off);
            if (lane == 0) g_bsum[blockIdx.x][b] = v;
        }
    }
}

// ---------------------------------------------------------------------------
// k3: final scalar, parallelized. Warp b (b<8) reduces g_bsum[:][b] and
// rowsum(sim[b]); thread 0 combines.
// ---------------------------------------------------------------------------
__global__ void k3_final(const float* __restrict__ sim,
                         float* __restrict__ out,
                         int nblocks)
{
    __shared__ float s_ss[8], s_rs[8];
    int warp = threadIdx.x >> 5, lane = threadIdx.x & 31;

    if (warp < 8) {
        float v = 0.f;
        for (int k = lane; k < nblocks; k += 32) v += g_bsum[k][warp];
        #pragma unroll
        for (int off = 16; off > 0; off >>= 1)
            v += __shfl_xor_sync(0xFFFFFFFFu, v, off);

        float r = (lane < 8) ? sim[warp * 8 + lane] : 0.f;
        #pragma unroll
        for (int off = 4; off > 0; off >>= 1)
            r += __shfl_xor_sync(0xFFFFFFFFu, r, off);

        if (lane == 0) { s_ss[warp] = v; s_rs[warp] = r; }
    }
    __syncthreads();
    if (threadIdx.x == 0) {
        float total = 0.f, cnt = 0.f;
        #pragma unroll
        for (int b = 0; b < 8; b++) {
            if (s_rs[b] != 0.f) {
                total += sqrtf(s_ss[b]);
                cnt   += 1.f;
            }
        }
        out[0] = (cnt == 0.f) ? 0.f : total / fmaxf(cnt, 1.f);
    }
}

// ---------------------------------------------------------------------------
extern "C" void kernel_launch(void* const* d_in, const int* in_sizes, int n_in,
                              void* d_out, int out_size)
{
    const float* predicts = (const float*)d_in[0];
    const float* sim      = (const float*)d_in[1];
    const float* adj      = (const float*)d_in[2];
    const float* mask     = (const float*)d_in[3];
    float*       out      = (float*)d_out;

    const int B = 8;
    const int L = in_sizes[0] / B;        // 12288

    k0_transpose<<<(L + 255) / 256, 256>>>(predicts, L);

    int colblocks = (L / 4) / K1_THREADS;                      // 24, exact
    dim3 g1(colblocks, SPLITS);                                // 24 x 64 = 1536
    k1_masked_gemv<<<g1, K1_THREADS>>>((const float4*)adj,
                                       (const float4*)mask, L);

    int k2blocks = (L + K2_THREADS - 1) / K2_THREADS;          // 48
    k2_epilogue<<<k2blocks, K2_THREADS>>>(predicts, sim, mask, L);

    k3_final<<<1, 256>>>(sim, out, k2blocks);
}